// round 2
// baseline (speedup 1.0000x reference)
#include <cuda_runtime.h>

#define BB 8
#define C 256
#define HID 64
#define G 16
#define KK 9
#define GKK 144
#define HW 4096
#define IMG_W 64
#define IMG_H 64

typedef unsigned long long u64;

// device scratch (allocation-free rule: __device__ globals)
__device__ __align__(16) float g_hid[BB * HID * HW];    // 8 MB
__device__ __align__(16) float g_kmap[BB * GKK * HW];   // 18 MB

__device__ __forceinline__ u64 ffma2(u64 a, u64 b, u64 c) {
    u64 d;
    asm("fma.rn.f32x2 %0, %1, %2, %3;" : "=l"(d) : "l"(a), "l"(b), "l"(c));
    return d;
}
__device__ __forceinline__ u64 pk(float lo, float hi) {
    u64 r;
    asm("mov.b64 %0, {%1, %2};" : "=l"(r) : "f"(lo), "f"(hi));
    return r;
}
__device__ __forceinline__ float lo32(u64 v) { return __uint_as_float((unsigned)(v & 0xFFFFFFFFu)); }
__device__ __forceinline__ float hi32(u64 v) { return __uint_as_float((unsigned)(v >> 32)); }

// ---------------------------------------------------------------------------
// Kernel 1: hid[b,o,p] = relu(sum_c w_reduce[o,c] * x[b,c,p] + b_reduce[o])
// 256 thr = 32 px-groups(4px) x 8 out-groups(8 outs). FFMA2 inner loop.
// ---------------------------------------------------------------------------
__global__ __launch_bounds__(256) void k_reduce(const float* __restrict__ x,
                                                const float* __restrict__ wr,
                                                const float* __restrict__ br) {
    __shared__ __align__(16) float xs[32 * 128];   // 16 KB
    __shared__ __align__(16) u64 ws2[64 * 32];     // 16 KB, {w,w} pairs
    const int tid = threadIdx.x;
    const int b  = blockIdx.x >> 5;
    const int pt = (blockIdx.x & 31) << 7;
    const int pg = tid & 31;
    const int og = tid >> 5;

    u64 acc[8][2];
#pragma unroll
    for (int i = 0; i < 8; i++) { acc[i][0] = 0ull; acc[i][1] = 0ull; }

    for (int ck = 0; ck < 8; ck++) {
#pragma unroll
        for (int i = 0; i < 4; i++) {
            int lin = tid + i * 256;
            int cc = lin >> 5, p4 = lin & 31;
            float4 v = *(const float4*)(x + ((size_t)(b * C + ck * 32 + cc)) * HW + pt + p4 * 4);
            *(float4*)(xs + cc * 128 + p4 * 4) = v;
        }
#pragma unroll
        for (int i = 0; i < 8; i++) {
            int lin = tid + i * 256;           // = o*32 + cc
            int o = lin >> 5, cc = lin & 31;
            unsigned u = __float_as_uint(wr[o * C + ck * 32 + cc]);
            ws2[lin] = (u64)u | ((u64)u << 32);
        }
        __syncthreads();
#pragma unroll
        for (int cc = 0; cc < 32; cc++) {
            ulonglong2 xv = *(const ulonglong2*)(xs + cc * 128 + pg * 4);
#pragma unroll
            for (int om = 0; om < 8; om++) {
                u64 wv = ws2[(og * 8 + om) * 32 + cc];  // warp-uniform broadcast
                acc[om][0] = ffma2(wv, xv.x, acc[om][0]);
                acc[om][1] = ffma2(wv, xv.y, acc[om][1]);
            }
        }
        __syncthreads();
    }
#pragma unroll
    for (int om = 0; om < 8; om++) {
        int o = og * 8 + om;
        float bias = __ldg(br + o);
        float4 r;
        r.x = fmaxf(lo32(acc[om][0]) + bias, 0.f);
        r.y = fmaxf(hi32(acc[om][0]) + bias, 0.f);
        r.z = fmaxf(lo32(acc[om][1]) + bias, 0.f);
        r.w = fmaxf(hi32(acc[om][1]) + bias, 0.f);
        *(float4*)(g_hid + ((size_t)(b * HID + o)) * HW + pt + pg * 4) = r;
    }
}

// ---------------------------------------------------------------------------
// Kernel 2: Kmap[b,o,p] = sum_h w_span[o,h] * hid[b,h,p] + b_span[o]
// 288 thr = 32 px-groups(4px) x 9 out-groups(16 outs). FFMA2, 4 chunks of 16.
// ---------------------------------------------------------------------------
__global__ __launch_bounds__(288) void k_span(const float* __restrict__ wsp,
                                              const float* __restrict__ bs) {
    __shared__ __align__(16) float hs[16 * 128];   // 8 KB
    __shared__ __align__(16) u64 ws2[144 * 16];    // 18 KB
    const int tid = threadIdx.x;
    const int b  = blockIdx.x >> 5;
    const int pt = (blockIdx.x & 31) << 7;
    const int pg = tid & 31;
    const int og = tid >> 5;                       // 0..8

    u64 acc[16][2];
#pragma unroll
    for (int i = 0; i < 16; i++) { acc[i][0] = 0ull; acc[i][1] = 0ull; }

    for (int hc = 0; hc < 4; hc++) {
        for (int idx = tid; idx < 16 * 128; idx += 288) {
            int hh = idx >> 7, p = idx & 127;
            hs[idx] = g_hid[((size_t)(b * HID + hc * 16 + hh)) * HW + pt + p];
        }
        for (int idx = tid; idx < 144 * 16; idx += 288) {
            int o = idx >> 4, hh = idx & 15;
            unsigned u = __float_as_uint(wsp[o * HID + hc * 16 + hh]);
            ws2[idx] = (u64)u | ((u64)u << 32);
        }
        __syncthreads();
#pragma unroll
        for (int hh = 0; hh < 16; hh++) {
            ulonglong2 xv = *(const ulonglong2*)(hs + hh * 128 + pg * 4);
#pragma unroll
            for (int om = 0; om < 16; om++) {
                u64 wv = ws2[(og * 16 + om) * 16 + hh];
                acc[om][0] = ffma2(wv, xv.x, acc[om][0]);
                acc[om][1] = ffma2(wv, xv.y, acc[om][1]);
            }
        }
        __syncthreads();
    }
#pragma unroll
    for (int om = 0; om < 16; om++) {
        int o = og * 16 + om;
        float bias = __ldg(bs + o);
        float4 r;
        r.x = lo32(acc[om][0]) + bias;
        r.y = hi32(acc[om][0]) + bias;
        r.z = lo32(acc[om][1]) + bias;
        r.w = hi32(acc[om][1]) + bias;
        *(float4*)(g_kmap + ((size_t)(b * GKK + o)) * HW + pt + pg * 4) = r;
    }
}

// ---------------------------------------------------------------------------
// Kernel 3: involution. Each thread: 4 adjacent pixels x 4 channels.
// Row segments loaded once (LDS.128 + LDS.64), reused across dx shifts.
// Kmap pairs (adjacent pixels) loaded as ulonglong2 -> FFMA2.
// 256 thr = 4 ch-groups x (16 rows x 4 col-groups).
// ---------------------------------------------------------------------------
__global__ __launch_bounds__(256) void k_invol(const float* __restrict__ x,
                                               float* __restrict__ out) {
    __shared__ __align__(16) float xs[16 * 18 * 20];  // [ch][row(18)][col stride 20], 23 KB
    const int tid = threadIdx.x;
    const int tile = blockIdx.x;              // 0..15
    const int g = blockIdx.y;
    const int b = blockIdx.z;
    const int ty = (tile >> 2) * 16;
    const int tx = (tile & 3) * 16;

    // cooperative load of 16ch x 18x18 halo tile (zero padded at borders)
    for (int idx = tid; idx < 16 * 18 * 18; idx += 256) {
        int ch  = idx / 324;
        int rem = idx - ch * 324;
        int r  = rem / 18;
        int cc = rem - r * 18;
        int Y = ty + r - 1, X = tx + cc - 1;
        float v = 0.f;
        if (Y >= 0 && Y < IMG_H && X >= 0 && X < IMG_W)
            v = x[((size_t)(b * C + g * 16 + ch)) * HW + Y * IMG_W + X];
        xs[ch * 360 + r * 20 + cc] = v;
    }
    __syncthreads();

    const int chg = tid >> 6;          // 0..3  -> channels chg*4 .. chg*4+3
    const int r6  = tid & 63;
    const int py  = r6 >> 2;           // 0..15
    const int px0 = (r6 & 3) * 4;      // 0,4,8,12
    const int Y = ty + py, X0 = tx + px0;

    // Kmap pairs: kv[k].x = {km[p0],km[p1]}, kv[k].y = {km[p2],km[p3]}
    ulonglong2 kv[9];
#pragma unroll
    for (int k = 0; k < 9; k++)
        kv[k] = *(const ulonglong2*)(g_kmap + ((((size_t)(b * G + g)) * KK + k) * HW) + Y * IMG_W + X0);

#pragma unroll
    for (int ci = 0; ci < 4; ci++) {
        const int ch = chg * 4 + ci;
        u64 accA = 0ull, accB = 0ull;   // (p0,p1) and (p2,p3)
        const float* base = xs + ch * 360 + py * 20 + px0;
#pragma unroll
        for (int dy = 0; dy < 3; dy++) {
            float4 a  = *(const float4*)(base + dy * 20);      // r0..r3
            float2 b2 = *(const float2*)(base + dy * 20 + 4);  // r4,r5
            u64 p01 = pk(a.x, a.y);
            u64 p12 = pk(a.y, a.z);
            u64 p23 = pk(a.z, a.w);
            u64 p34 = pk(a.w, b2.x);
            u64 p45 = pk(b2.x, b2.y);
            accA = ffma2(p01, kv[dy * 3 + 0].x, accA);
            accA = ffma2(p12, kv[dy * 3 + 1].x, accA);
            accA = ffma2(p23, kv[dy * 3 + 2].x, accA);
            accB = ffma2(p23, kv[dy * 3 + 0].y, accB);
            accB = ffma2(p34, kv[dy * 3 + 1].y, accB);
            accB = ffma2(p45, kv[dy * 3 + 2].y, accB);
        }
        float4 r;
        r.x = lo32(accA); r.y = hi32(accA);
        r.z = lo32(accB); r.w = hi32(accB);
        *(float4*)(out + ((size_t)(b * C + g * 16 + ch)) * HW + Y * IMG_W + X0) = r;
    }
}

// ---------------------------------------------------------------------------
extern "C" void kernel_launch(void* const* d_in, const int* in_sizes, int n_in,
                              void* d_out, int out_size) {
    const float* x   = (const float*)d_in[0];
    const float* wr  = (const float*)d_in[1];
    const float* br  = (const float*)d_in[2];
    const float* wsp = (const float*)d_in[3];
    const float* bs  = (const float*)d_in[4];
    float* out = (float*)d_out;

    k_reduce<<<BB * (HW / 128), 256>>>(x, wr, br);
    k_span<<<BB * (HW / 128), 288>>>(wsp, bs);
    dim3 g3(16, G, BB);
    k_invol<<<g3, 256>>>(x, out);
}

// round 3
// speedup vs baseline: 1.2153x; 1.2153x over previous
#include <cuda_runtime.h>

#define BB 8
#define C 256
#define HID 64
#define G 16
#define KK 9
#define GKK 144
#define HW 4096
#define IMG_W 64
#define IMG_H 64

typedef unsigned long long u64;

__device__ __align__(16) float g_kmap[BB * GKK * HW];   // 18 MB scratch

__device__ __forceinline__ u64 ffma2(u64 a, u64 b, u64 c) {
    u64 d;
    asm("fma.rn.f32x2 %0, %1, %2, %3;" : "=l"(d) : "l"(a), "l"(b), "l"(c));
    return d;
}
__device__ __forceinline__ u64 pk(float lo, float hi) {
    u64 r;
    asm("mov.b64 %0, {%1, %2};" : "=l"(r) : "f"(lo), "f"(hi));
    return r;
}
__device__ __forceinline__ float lo32(u64 v) { return __uint_as_float((unsigned)(v & 0xFFFFFFFFu)); }
__device__ __forceinline__ float hi32(u64 v) { return __uint_as_float((unsigned)(v >> 32)); }

// ---------------------------------------------------------------------------
// Fused kernel: stage1 (reduce+relu) -> smem hid -> stage2 (span) -> g_kmap
// CTA: one batch, 128-pixel tile. 256 threads = 32 px-groups(4 px) x 8 warps.
// Phase A: each warp computes 8 hid rows, double-buffered x/w chunk loads.
// Phase B: each warp computes 18 kmap rows from smem hid.
//
// dynamic smem (floats):
//   [0,     4096)  ws[2][64*32]    phase A w chunks (16KB)
//   [4096, 12288)  xs[2][32*128]   phase A x chunks (32KB)
//   [0,     8192)  hid[64*128]     phase B (reuses A region, 32KB)
//   [12288,21504)  wsp_s[144*64]   w_span (36KB)
// total 21504 floats = 84KB -> 2 CTAs/SM
// ---------------------------------------------------------------------------
__global__ __launch_bounds__(256, 2) void k_fused(const float* __restrict__ x,
                                                  const float* __restrict__ wr,
                                                  const float* __restrict__ br,
                                                  const float* __restrict__ wsp,
                                                  const float* __restrict__ bs) {
    extern __shared__ __align__(16) float sm[];
    float* ws    = sm;              // [2][2048]
    float* xs    = sm + 4096;       // [2][4096]
    float* hid   = sm;              // [64][128] (phase B)
    float* wsp_s = sm + 12288;      // [144][64]

    const int tid = threadIdx.x;
    const int b  = blockIdx.x >> 5;
    const int pt = (blockIdx.x & 31) << 7;
    const int pg = tid & 31;
    const int og = tid >> 5;

    // one-time: stream w_span into smem (coalesced, [144][64] row-major == src)
#pragma unroll
    for (int i = 0; i < 36; i++)
        wsp_s[tid + i * 256] = wsp[tid + i * 256];

    // ---- phase A prologue: chunk 0 into buffer 0 ----
    {
#pragma unroll
        for (int i = 0; i < 4; i++) {
            int lin = tid + i * 256;
            int cc = lin >> 5, p4 = lin & 31;
            float4 v = *(const float4*)(x + ((size_t)(b * C + cc)) * HW + pt + p4 * 4);
            *(float4*)(xs + cc * 128 + p4 * 4) = v;
        }
#pragma unroll
        for (int i = 0; i < 8; i++) {
            int lin = tid + i * 256;        // = o*32 + cc
            int o = lin >> 5, cc = lin & 31;
            ws[lin] = wr[o * C + cc];
        }
    }
    __syncthreads();

    float acc[8][4];
#pragma unroll
    for (int i = 0; i < 8; i++)
#pragma unroll
        for (int j = 0; j < 4; j++) acc[i][j] = 0.f;

    // ---- phase A main loop: double buffered ----
    for (int ck = 0; ck < 8; ck++) {
        const int cur = ck & 1;
        float4 xr[4];
        float  wrr[8];
        if (ck < 7) {
#pragma unroll
            for (int i = 0; i < 4; i++) {
                int lin = tid + i * 256;
                int cc = lin >> 5, p4 = lin & 31;
                xr[i] = *(const float4*)(x + ((size_t)(b * C + (ck + 1) * 32 + cc)) * HW + pt + p4 * 4);
            }
#pragma unroll
            for (int i = 0; i < 8; i++) {
                int lin = tid + i * 256;
                int o = lin >> 5, cc = lin & 31;
                wrr[i] = wr[o * C + (ck + 1) * 32 + cc];
            }
        }
        const float* xb = xs + cur * 4096;
        const float* wb = ws + cur * 2048;
#pragma unroll
        for (int cc = 0; cc < 32; cc++) {
            float4 xv = *(const float4*)(xb + cc * 128 + pg * 4);
#pragma unroll
            for (int om = 0; om < 8; om++) {
                float wv = wb[(og * 8 + om) * 32 + cc];   // warp-uniform broadcast
                acc[om][0] = fmaf(wv, xv.x, acc[om][0]);
                acc[om][1] = fmaf(wv, xv.y, acc[om][1]);
                acc[om][2] = fmaf(wv, xv.z, acc[om][2]);
                acc[om][3] = fmaf(wv, xv.w, acc[om][3]);
            }
        }
        if (ck < 7) {
            const int nxt = cur ^ 1;
#pragma unroll
            for (int i = 0; i < 4; i++) {
                int lin = tid + i * 256;
                int cc = lin >> 5, p4 = lin & 31;
                *(float4*)(xs + nxt * 4096 + cc * 128 + p4 * 4) = xr[i];
            }
#pragma unroll
            for (int i = 0; i < 8; i++)
                ws[nxt * 2048 + tid + i * 256] = wrr[i];
        }
        __syncthreads();   // also serves as pre-epilogue barrier on last iter
    }

    // ---- phase A epilogue: relu+bias -> smem hid (overwrites ws/xs[0]) ----
#pragma unroll
    for (int om = 0; om < 8; om++) {
        int o = og * 8 + om;
        float bias = __ldg(br + o);
        float4 r;
        r.x = fmaxf(acc[om][0] + bias, 0.f);
        r.y = fmaxf(acc[om][1] + bias, 0.f);
        r.z = fmaxf(acc[om][2] + bias, 0.f);
        r.w = fmaxf(acc[om][3] + bias, 0.f);
        *(float4*)(hid + o * 128 + pg * 4) = r;
    }
    __syncthreads();

    // ---- phase B: kmap[o,p] = sum_hh wsp[o,hh]*hid[hh,p] + bs[o], o = og*18+om ----
    float acc2[18][4];
#pragma unroll
    for (int i = 0; i < 18; i++)
#pragma unroll
        for (int j = 0; j < 4; j++) acc2[i][j] = 0.f;

#pragma unroll 8
    for (int hh = 0; hh < 64; hh++) {
        float4 xv = *(const float4*)(hid + hh * 128 + pg * 4);
#pragma unroll
        for (int om = 0; om < 18; om++) {
            float wv = wsp_s[(og * 18 + om) * 64 + hh];   // warp-uniform broadcast
            acc2[om][0] = fmaf(wv, xv.x, acc2[om][0]);
            acc2[om][1] = fmaf(wv, xv.y, acc2[om][1]);
            acc2[om][2] = fmaf(wv, xv.z, acc2[om][2]);
            acc2[om][3] = fmaf(wv, xv.w, acc2[om][3]);
        }
    }
#pragma unroll
    for (int om = 0; om < 18; om++) {
        int o = og * 18 + om;
        float bias = __ldg(bs + o);
        float4 r;
        r.x = acc2[om][0] + bias;
        r.y = acc2[om][1] + bias;
        r.z = acc2[om][2] + bias;
        r.w = acc2[om][3] + bias;
        *(float4*)(g_kmap + ((size_t)(b * GKK + o)) * HW + pt + pg * 4) = r;
    }
}

// ---------------------------------------------------------------------------
// Kernel 3: involution. Each thread: 4 adjacent pixels x 4 channels.
// Row segments loaded once (LDS.128 + LDS.64), reused across dx shifts; FFMA2.
// ---------------------------------------------------------------------------
__global__ __launch_bounds__(256) void k_invol(const float* __restrict__ x,
                                               float* __restrict__ out) {
    __shared__ __align__(16) float xs[16 * 18 * 20];  // [ch][row(18)][col stride 20]
    const int tid = threadIdx.x;
    const int tile = blockIdx.x;              // 0..15
    const int g = blockIdx.y;
    const int b = blockIdx.z;
    const int ty = (tile >> 2) * 16;
    const int tx = (tile & 3) * 16;

    for (int idx = tid; idx < 16 * 18 * 18; idx += 256) {
        int ch  = idx / 324;
        int rem = idx - ch * 324;
        int r  = rem / 18;
        int cc = rem - r * 18;
        int Y = ty + r - 1, X = tx + cc - 1;
        float v = 0.f;
        if (Y >= 0 && Y < IMG_H && X >= 0 && X < IMG_W)
            v = x[((size_t)(b * C + g * 16 + ch)) * HW + Y * IMG_W + X];
        xs[ch * 360 + r * 20 + cc] = v;
    }
    __syncthreads();

    const int chg = tid >> 6;          // 0..3  -> channels chg*4 .. chg*4+3
    const int r6  = tid & 63;
    const int py  = r6 >> 2;           // 0..15
    const int px0 = (r6 & 3) * 4;      // 0,4,8,12
    const int Y = ty + py, X0 = tx + px0;

    ulonglong2 kv[9];
#pragma unroll
    for (int k = 0; k < 9; k++)
        kv[k] = *(const ulonglong2*)(g_kmap + ((((size_t)(b * G + g)) * KK + k) * HW) + Y * IMG_W + X0);

#pragma unroll
    for (int ci = 0; ci < 4; ci++) {
        const int ch = chg * 4 + ci;
        u64 accA = 0ull, accB = 0ull;
        const float* base = xs + ch * 360 + py * 20 + px0;
#pragma unroll
        for (int dy = 0; dy < 3; dy++) {
            float4 a  = *(const float4*)(base + dy * 20);
            float2 b2 = *(const float2*)(base + dy * 20 + 4);
            u64 p01 = pk(a.x, a.y);
            u64 p12 = pk(a.y, a.z);
            u64 p23 = pk(a.z, a.w);
            u64 p34 = pk(a.w, b2.x);
            u64 p45 = pk(b2.x, b2.y);
            accA = ffma2(p01, kv[dy * 3 + 0].x, accA);
            accA = ffma2(p12, kv[dy * 3 + 1].x, accA);
            accA = ffma2(p23, kv[dy * 3 + 2].x, accA);
            accB = ffma2(p23, kv[dy * 3 + 0].y, accB);
            accB = ffma2(p34, kv[dy * 3 + 1].y, accB);
            accB = ffma2(p45, kv[dy * 3 + 2].y, accB);
        }
        float4 r;
        r.x = lo32(accA); r.y = hi32(accA);
        r.z = lo32(accB); r.w = hi32(accB);
        *(float4*)(out + ((size_t)(b * C + g * 16 + ch)) * HW + Y * IMG_W + X0) = r;
    }
}

// ---------------------------------------------------------------------------
extern "C" void kernel_launch(void* const* d_in, const int* in_sizes, int n_in,
                              void* d_out, int out_size) {
    const float* x   = (const float*)d_in[0];
    const float* wr  = (const float*)d_in[1];
    const float* br  = (const float*)d_in[2];
    const float* wsp = (const float*)d_in[3];
    const float* bs  = (const float*)d_in[4];
    float* out = (float*)d_out;

    static int smem_set = 0;
    if (!smem_set) {
        cudaFuncSetAttribute(k_fused, cudaFuncAttributeMaxDynamicSharedMemorySize, 86016);
        smem_set = 1;
    }

    k_fused<<<BB * (HW / 128), 256, 86016>>>(x, wr, br, wsp, bs);
    dim3 g3(16, G, BB);
    k_invol<<<g3, 256>>>(x, out);
}

// round 4
// speedup vs baseline: 1.4751x; 1.2138x over previous
#include <cuda_runtime.h>

#define BB 8
#define C 256
#define HID 64
#define G 16
#define KK 9
#define GKK 144
#define HW 4096
#define IMG_W 64
#define IMG_H 64

typedef unsigned long long u64;

__device__ __align__(16) float g_kmap[BB * GKK * HW];   // 18 MB scratch

__device__ __forceinline__ u64 ffma2(u64 a, u64 b, u64 c) {
    u64 d;
    asm("fma.rn.f32x2 %0, %1, %2, %3;" : "=l"(d) : "l"(a), "l"(b), "l"(c));
    return d;
}
__device__ __forceinline__ u64 pk(float lo, float hi) {
    u64 r;
    asm("mov.b64 %0, {%1, %2};" : "=l"(r) : "f"(lo), "f"(hi));
    return r;
}
__device__ __forceinline__ float lo32(u64 v) { return __uint_as_float((unsigned)(v & 0xFFFFFFFFu)); }
__device__ __forceinline__ float hi32(u64 v) { return __uint_as_float((unsigned)(v >> 32)); }

// ---------------------------------------------------------------------------
// Fused kernel: stage1 (reduce+relu) -> smem hid -> stage2 (span) -> g_kmap
// Weights loaded as float4 (warp-uniform LDS.128 broadcast) -> high FFMA density.
// ---------------------------------------------------------------------------
__global__ __launch_bounds__(256, 2) void k_fused(const float* __restrict__ x,
                                                  const float* __restrict__ wr,
                                                  const float* __restrict__ br,
                                                  const float* __restrict__ wsp,
                                                  const float* __restrict__ bs) {
    extern __shared__ __align__(16) float sm[];
    float* ws    = sm;              // [2][2048]  phase A w chunks
    float* xs    = sm + 4096;       // [2][4096]  phase A x chunks
    float* hid   = sm;              // [64][128]  phase B (reuses A region)
    float* wsp_s = sm + 12288;      // [144][64]

    const int tid = threadIdx.x;
    const int b  = blockIdx.x >> 5;
    const int pt = (blockIdx.x & 31) << 7;
    const int pg = tid & 31;
    const int og = tid >> 5;

    // stream w_span into smem (float4, coalesced)
#pragma unroll
    for (int i = 0; i < 9; i++) {
        int lin = (tid + i * 256) * 4;
        *(float4*)(wsp_s + lin) = *(const float4*)(wsp + lin);
    }

    // ---- phase A prologue: chunk 0 -> buffer 0 ----
#pragma unroll
    for (int i = 0; i < 4; i++) {
        int lin = tid + i * 256;
        int cc = lin >> 5, p4 = lin & 31;
        *(float4*)(xs + cc * 128 + p4 * 4) =
            *(const float4*)(x + ((size_t)(b * C + cc)) * HW + pt + p4 * 4);
    }
#pragma unroll
    for (int i = 0; i < 8; i++) {
        int lin = tid + i * 256;        // = o*32 + cc
        int o = lin >> 5, cc = lin & 31;
        ws[lin] = wr[o * C + cc];
    }
    __syncthreads();

    float acc[8][4];
#pragma unroll
    for (int i = 0; i < 8; i++)
#pragma unroll
        for (int j = 0; j < 4; j++) acc[i][j] = 0.f;

    // ---- phase A: double buffered, weights via float4 broadcast ----
    for (int ck = 0; ck < 8; ck++) {
        const int cur = ck & 1;
        float4 xr[4];
        float  wrr[8];
        if (ck < 7) {
#pragma unroll
            for (int i = 0; i < 4; i++) {
                int lin = tid + i * 256;
                int cc = lin >> 5, p4 = lin & 31;
                xr[i] = *(const float4*)(x + ((size_t)(b * C + (ck + 1) * 32 + cc)) * HW + pt + p4 * 4);
            }
#pragma unroll
            for (int i = 0; i < 8; i++) {
                int lin = tid + i * 256;
                int o = lin >> 5, cc = lin & 31;
                wrr[i] = wr[o * C + (ck + 1) * 32 + cc];
            }
        }
        const float* xb = xs + cur * 4096;
        const float* wb = ws + cur * 2048;
#pragma unroll
        for (int cb = 0; cb < 8; cb++) {
            float4 xv[4];
#pragma unroll
            for (int i = 0; i < 4; i++)
                xv[i] = *(const float4*)(xb + (cb * 4 + i) * 128 + pg * 4);
#pragma unroll
            for (int om = 0; om < 8; om++) {
                float4 wv = *(const float4*)(wb + (og * 8 + om) * 32 + cb * 4); // uniform bcast
                acc[om][0] = fmaf(wv.x, xv[0].x, acc[om][0]);
                acc[om][1] = fmaf(wv.x, xv[0].y, acc[om][1]);
                acc[om][2] = fmaf(wv.x, xv[0].z, acc[om][2]);
                acc[om][3] = fmaf(wv.x, xv[0].w, acc[om][3]);
                acc[om][0] = fmaf(wv.y, xv[1].x, acc[om][0]);
                acc[om][1] = fmaf(wv.y, xv[1].y, acc[om][1]);
                acc[om][2] = fmaf(wv.y, xv[1].z, acc[om][2]);
                acc[om][3] = fmaf(wv.y, xv[1].w, acc[om][3]);
                acc[om][0] = fmaf(wv.z, xv[2].x, acc[om][0]);
                acc[om][1] = fmaf(wv.z, xv[2].y, acc[om][1]);
                acc[om][2] = fmaf(wv.z, xv[2].z, acc[om][2]);
                acc[om][3] = fmaf(wv.z, xv[2].w, acc[om][3]);
                acc[om][0] = fmaf(wv.w, xv[3].x, acc[om][0]);
                acc[om][1] = fmaf(wv.w, xv[3].y, acc[om][1]);
                acc[om][2] = fmaf(wv.w, xv[3].z, acc[om][2]);
                acc[om][3] = fmaf(wv.w, xv[3].w, acc[om][3]);
            }
        }
        if (ck < 7) {
            const int nxt = cur ^ 1;
#pragma unroll
            for (int i = 0; i < 4; i++) {
                int lin = tid + i * 256;
                int cc = lin >> 5, p4 = lin & 31;
                *(float4*)(xs + nxt * 4096 + cc * 128 + p4 * 4) = xr[i];
            }
#pragma unroll
            for (int i = 0; i < 8; i++)
                ws[nxt * 2048 + tid + i * 256] = wrr[i];
        }
        __syncthreads();
    }

    // ---- phase A epilogue: relu+bias -> smem hid ----
#pragma unroll
    for (int om = 0; om < 8; om++) {
        int o = og * 8 + om;
        float bias = __ldg(br + o);
        float4 r;
        r.x = fmaxf(acc[om][0] + bias, 0.f);
        r.y = fmaxf(acc[om][1] + bias, 0.f);
        r.z = fmaxf(acc[om][2] + bias, 0.f);
        r.w = fmaxf(acc[om][3] + bias, 0.f);
        *(float4*)(hid + o * 128 + pg * 4) = r;
    }
    __syncthreads();

    // ---- phase B: span GEMM, weights via float4 broadcast ----
    float acc2[18][4];
#pragma unroll
    for (int i = 0; i < 18; i++)
#pragma unroll
        for (int j = 0; j < 4; j++) acc2[i][j] = 0.f;

#pragma unroll 4
    for (int hb = 0; hb < 16; hb++) {
        float4 xv[4];
#pragma unroll
        for (int i = 0; i < 4; i++)
            xv[i] = *(const float4*)(hid + (hb * 4 + i) * 128 + pg * 4);
#pragma unroll
        for (int om = 0; om < 18; om++) {
            float4 wv = *(const float4*)(wsp_s + (og * 18 + om) * 64 + hb * 4); // uniform bcast
            acc2[om][0] = fmaf(wv.x, xv[0].x, acc2[om][0]);
            acc2[om][1] = fmaf(wv.x, xv[0].y, acc2[om][1]);
            acc2[om][2] = fmaf(wv.x, xv[0].z, acc2[om][2]);
            acc2[om][3] = fmaf(wv.x, xv[0].w, acc2[om][3]);
            acc2[om][0] = fmaf(wv.y, xv[1].x, acc2[om][0]);
            acc2[om][1] = fmaf(wv.y, xv[1].y, acc2[om][1]);
            acc2[om][2] = fmaf(wv.y, xv[1].z, acc2[om][2]);
            acc2[om][3] = fmaf(wv.y, xv[1].w, acc2[om][3]);
            acc2[om][0] = fmaf(wv.z, xv[2].x, acc2[om][0]);
            acc2[om][1] = fmaf(wv.z, xv[2].y, acc2[om][1]);
            acc2[om][2] = fmaf(wv.z, xv[2].z, acc2[om][2]);
            acc2[om][3] = fmaf(wv.z, xv[2].w, acc2[om][3]);
            acc2[om][0] = fmaf(wv.w, xv[3].x, acc2[om][0]);
            acc2[om][1] = fmaf(wv.w, xv[3].y, acc2[om][1]);
            acc2[om][2] = fmaf(wv.w, xv[3].z, acc2[om][2]);
            acc2[om][3] = fmaf(wv.w, xv[3].w, acc2[om][3]);
        }
    }
#pragma unroll
    for (int om = 0; om < 18; om++) {
        int o = og * 18 + om;
        float bias = __ldg(bs + o);
        float4 r;
        r.x = acc2[om][0] + bias;
        r.y = acc2[om][1] + bias;
        r.z = acc2[om][2] + bias;
        r.w = acc2[om][3] + bias;
        *(float4*)(g_kmap + ((size_t)(b * GKK + o)) * HW + pt + pg * 4) = r;
    }
}

// ---------------------------------------------------------------------------
// Kernel 3: involution, channel-pair interleaved smem.
// CTA = (b, g, ch-half of 8, row-strip of 8). smem [4 chpair][10 rows][68 cols][2].
// Full-width rows: float4-coalesced loads, no horizontal bounds checks.
// FFMA2 over channel pairs: operands are aligned LDS.128, no per-element packing.
// 256 thr = (cph:2) x (row:8) x (colgroup:16 of 4 cols). 16 outputs/thread.
// ---------------------------------------------------------------------------
__global__ __launch_bounds__(256) void k_invol(const float* __restrict__ x,
                                               float* __restrict__ out) {
    __shared__ __align__(16) float sm[4 * 10 * 68 * 2];   // 21.76 KB
    const int tid   = threadIdx.x;
    const int strip = blockIdx.x & 7;
    const int half  = blockIdx.x >> 3;      // 0..1
    const int g = blockIdx.y;
    const int b = blockIdx.z;
    const int chbase = g * 16 + half * 8;

    // zero edge pair-columns (smem col 0 and 65) for all (cp, r)
    if (tid < 80) {
        int cp = tid / 20, rem = tid % 20;
        int r = rem >> 1, side = rem & 1;
        int col = side ? 65 : 0;
        *(u64*)&sm[((cp * 10 + r) * 68 + col) * 2] = 0ull;
    }

    // load 4 chpairs x 10 rows x 64 cols, interleaving channel pairs
#pragma unroll
    for (int it = 0; it < 3; it++) {
        int lin = tid + it * 256;
        if (lin < 640) {
            int cp  = lin / 160;
            int rem = lin - cp * 160;
            int r = rem >> 4, t4 = rem & 15;
            int R = strip * 8 + r - 1;
            float4 a = make_float4(0.f, 0.f, 0.f, 0.f);
            float4 c = a;
            if ((unsigned)R < (unsigned)IMG_H) {
                const float* p0 = x + ((size_t)(b * C + chbase + cp * 2)) * HW + R * IMG_W + t4 * 4;
                a = *(const float4*)p0;
                c = *(const float4*)(p0 + HW);
            }
            float* d = &sm[((cp * 10 + r) * 68 + 1 + t4 * 4) * 2];
            ((float2*)d)[0] = make_float2(a.x, c.x);
            ((float2*)d)[1] = make_float2(a.y, c.y);
            ((float2*)d)[2] = make_float2(a.z, c.z);
            ((float2*)d)[3] = make_float2(a.w, c.w);
        }
    }
    __syncthreads();

    const int cph = tid >> 7;          // 0..1 -> chpairs cph*2, cph*2+1
    const int rr  = (tid >> 4) & 7;    // output row within strip
    const int t4  = tid & 15;          // colgroup (4 cols)
    const int R0  = strip * 8 + rr;
    const int X0  = t4 * 4;

    u64 acc[2][4];
#pragma unroll
    for (int cp = 0; cp < 2; cp++)
#pragma unroll
        for (int j = 0; j < 4; j++) acc[cp][j] = 0ull;

    const float* kbase = g_kmap + ((size_t)(b * G + g)) * KK * HW + R0 * IMG_W + X0;

#pragma unroll
    for (int dy = 0; dy < 3; dy++) {
        float4 km[3];
#pragma unroll
        for (int dx = 0; dx < 3; dx++)
            km[dx] = *(const float4*)(kbase + (size_t)(dy * 3 + dx) * HW);
        u64 km2[3][4];
#pragma unroll
        for (int dx = 0; dx < 3; dx++) {
            km2[dx][0] = pk(km[dx].x, km[dx].x);
            km2[dx][1] = pk(km[dx].y, km[dx].y);
            km2[dx][2] = pk(km[dx].z, km[dx].z);
            km2[dx][3] = pk(km[dx].w, km[dx].w);
        }
#pragma unroll
        for (int cp = 0; cp < 2; cp++) {
            const int cpi = cph * 2 + cp;
            const float* srow = &sm[((cpi * 10 + rr + dy) * 68 + t4 * 4) * 2];
            ulonglong2 q0 = *(const ulonglong2*)(srow);
            ulonglong2 q1 = *(const ulonglong2*)(srow + 4);
            ulonglong2 q2 = *(const ulonglong2*)(srow + 8);
            u64 p0 = q0.x, p1 = q0.y, p2 = q1.x, p3 = q1.y, p4 = q2.x, p5 = q2.y;
            acc[cp][0] = ffma2(p0, km2[0][0], acc[cp][0]);
            acc[cp][0] = ffma2(p1, km2[1][0], acc[cp][0]);
            acc[cp][0] = ffma2(p2, km2[2][0], acc[cp][0]);
            acc[cp][1] = ffma2(p1, km2[0][1], acc[cp][1]);
            acc[cp][1] = ffma2(p2, km2[1][1], acc[cp][1]);
            acc[cp][1] = ffma2(p3, km2[2][1], acc[cp][1]);
            acc[cp][2] = ffma2(p2, km2[0][2], acc[cp][2]);
            acc[cp][2] = ffma2(p3, km2[1][2], acc[cp][2]);
            acc[cp][2] = ffma2(p4, km2[2][2], acc[cp][2]);
            acc[cp][3] = ffma2(p3, km2[0][3], acc[cp][3]);
            acc[cp][3] = ffma2(p4, km2[1][3], acc[cp][3]);
            acc[cp][3] = ffma2(p5, km2[2][3], acc[cp][3]);
        }
    }

#pragma unroll
    for (int cp = 0; cp < 2; cp++) {
        const int ch = chbase + (cph * 2 + cp) * 2;
        float4 ev, od;
        ev.x = lo32(acc[cp][0]); od.x = hi32(acc[cp][0]);
        ev.y = lo32(acc[cp][1]); od.y = hi32(acc[cp][1]);
        ev.z = lo32(acc[cp][2]); od.z = hi32(acc[cp][2]);
        ev.w = lo32(acc[cp][3]); od.w = hi32(acc[cp][3]);
        float* obase = out + ((size_t)(b * C + ch)) * HW + R0 * IMG_W + X0;
        *(float4*)obase = ev;
        *(float4*)(obase + HW) = od;
    }
}

// ---------------------------------------------------------------------------
extern "C" void kernel_launch(void* const* d_in, const int* in_sizes, int n_in,
                              void* d_out, int out_size) {
    const float* x   = (const float*)d_in[0];
    const float* wr  = (const float*)d_in[1];
    const float* br  = (const float*)d_in[2];
    const float* wsp = (const float*)d_in[3];
    const float* bs  = (const float*)d_in[4];
    float* out = (float*)d_out;

    static int smem_set = 0;
    if (!smem_set) {
        cudaFuncSetAttribute(k_fused, cudaFuncAttributeMaxDynamicSharedMemorySize, 86016);
        smem_set = 1;
    }

    k_fused<<<BB * (HW / 128), 256, 86016>>>(x, wr, br, wsp, bs);
    dim3 g3(16, G, BB);   // (strip*half, g, b)
    k_invol<<<g3, 256>>>(x, out);
}

// round 6
// speedup vs baseline: 1.5282x; 1.0360x over previous
#include <cuda_runtime.h>

#define BB 8
#define C 256
#define HID 64
#define G 16
#define KK 9
#define GKK 144
#define HW 4096
#define IMG_W 64
#define IMG_H 64

typedef unsigned long long u64;

__device__ __align__(16) float g_kmap[BB * GKK * HW];   // 18 MB scratch

__device__ __forceinline__ u64 ffma2(u64 a, u64 b, u64 c) {
    u64 d;
    asm("fma.rn.f32x2 %0, %1, %2, %3;" : "=l"(d) : "l"(a), "l"(b), "l"(c));
    return d;
}
__device__ __forceinline__ u64 pk(float lo, float hi) {
    u64 r;
    asm("mov.b64 %0, {%1, %2};" : "=l"(r) : "f"(lo), "f"(hi));
    return r;
}
__device__ __forceinline__ float lo32(u64 v) { return __uint_as_float((unsigned)(v & 0xFFFFFFFFu)); }
__device__ __forceinline__ float hi32(u64 v) { return __uint_as_float((unsigned)(v >> 32)); }

// ---------------------------------------------------------------------------
// Fused kernel: stage1 (reduce+relu) -> smem hid -> stage2 (span) -> g_kmap
// Both GEMM phases use packed fma.rn.f32x2 (2 FMA/instr), weights broadcast
// from smem as float4 and duplicated into pairs via ALU-pipe movs.
// ---------------------------------------------------------------------------
__global__ __launch_bounds__(256, 2) void k_fused(const float* __restrict__ x,
                                                  const float* __restrict__ wr,
                                                  const float* __restrict__ br,
                                                  const float* __restrict__ wsp,
                                                  const float* __restrict__ bs) {
    extern __shared__ __align__(16) float sm[];
    float* ws    = sm;              // [2][2048]  phase A w chunks
    float* xs    = sm + 4096;       // [2][4096]  phase A x chunks
    float* hid   = sm;              // [64][128]  phase B (reuses A region)
    float* wsp_s = sm + 12288;      // [144][64]

    const int tid = threadIdx.x;
    const int b  = blockIdx.x >> 5;
    const int pt = (blockIdx.x & 31) << 7;
    const int pg = tid & 31;
    const int og = tid >> 5;

    // stream w_span into smem (float4, coalesced)
#pragma unroll
    for (int i = 0; i < 9; i++) {
        int lin = (tid + i * 256) * 4;
        *(float4*)(wsp_s + lin) = *(const float4*)(wsp + lin);
    }

    // ---- phase A prologue: chunk 0 -> buffer 0 ----
#pragma unroll
    for (int i = 0; i < 4; i++) {
        int lin = tid + i * 256;
        int cc = lin >> 5, p4 = lin & 31;
        *(float4*)(xs + cc * 128 + p4 * 4) =
            *(const float4*)(x + ((size_t)(b * C + cc)) * HW + pt + p4 * 4);
    }
#pragma unroll
    for (int i = 0; i < 8; i++) {
        int lin = tid + i * 256;        // = o*32 + cc
        int o = lin >> 5, cc = lin & 31;
        ws[lin] = wr[o * C + cc];
    }
    __syncthreads();

    u64 acc[8][2];
#pragma unroll
    for (int i = 0; i < 8; i++) { acc[i][0] = 0ull; acc[i][1] = 0ull; }

    // ---- phase A: double buffered, FFMA2 ----
    for (int ck = 0; ck < 8; ck++) {
        const int cur = ck & 1;
        float4 xr[4];
        float  wrr[8];
        if (ck < 7) {
#pragma unroll
            for (int i = 0; i < 4; i++) {
                int lin = tid + i * 256;
                int cc = lin >> 5, p4 = lin & 31;
                xr[i] = *(const float4*)(x + ((size_t)(b * C + (ck + 1) * 32 + cc)) * HW + pt + p4 * 4);
            }
#pragma unroll
            for (int i = 0; i < 8; i++) {
                int lin = tid + i * 256;
                int o = lin >> 5, cc = lin & 31;
                wrr[i] = wr[o * C + (ck + 1) * 32 + cc];
            }
        }
        const float* xb = xs + cur * 4096;
        const float* wb = ws + cur * 2048;
#pragma unroll
        for (int cb = 0; cb < 8; cb++) {
            ulonglong2 xq[4];
#pragma unroll
            for (int i = 0; i < 4; i++)
                xq[i] = *(const ulonglong2*)(xb + (cb * 4 + i) * 128 + pg * 4);
#pragma unroll
            for (int om = 0; om < 8; om++) {
                float4 wv = *(const float4*)(wb + (og * 8 + om) * 32 + cb * 4); // uniform bcast
                u64 w0 = pk(wv.x, wv.x), w1 = pk(wv.y, wv.y);
                u64 w2 = pk(wv.z, wv.z), w3 = pk(wv.w, wv.w);
                acc[om][0] = ffma2(w0, xq[0].x, acc[om][0]);
                acc[om][1] = ffma2(w0, xq[0].y, acc[om][1]);
                acc[om][0] = ffma2(w1, xq[1].x, acc[om][0]);
                acc[om][1] = ffma2(w1, xq[1].y, acc[om][1]);
                acc[om][0] = ffma2(w2, xq[2].x, acc[om][0]);
                acc[om][1] = ffma2(w2, xq[2].y, acc[om][1]);
                acc[om][0] = ffma2(w3, xq[3].x, acc[om][0]);
                acc[om][1] = ffma2(w3, xq[3].y, acc[om][1]);
            }
        }
        if (ck < 7) {
            const int nxt = cur ^ 1;
#pragma unroll
            for (int i = 0; i < 4; i++) {
                int lin = tid + i * 256;
                int cc = lin >> 5, p4 = lin & 31;
                *(float4*)(xs + nxt * 4096 + cc * 128 + p4 * 4) = xr[i];
            }
#pragma unroll
            for (int i = 0; i < 8; i++)
                ws[nxt * 2048 + tid + i * 256] = wrr[i];
        }
        __syncthreads();
    }

    // ---- phase A epilogue: relu+bias -> smem hid ----
#pragma unroll
    for (int om = 0; om < 8; om++) {
        int o = og * 8 + om;
        float bias = __ldg(br + o);
        float4 r;
        r.x = fmaxf(lo32(acc[om][0]) + bias, 0.f);
        r.y = fmaxf(hi32(acc[om][0]) + bias, 0.f);
        r.z = fmaxf(lo32(acc[om][1]) + bias, 0.f);
        r.w = fmaxf(hi32(acc[om][1]) + bias, 0.f);
        *(float4*)(hid + o * 128 + pg * 4) = r;
    }
    __syncthreads();

    // ---- phase B: span GEMM, FFMA2 ----
    u64 acc2[18][2];
#pragma unroll
    for (int i = 0; i < 18; i++) { acc2[i][0] = 0ull; acc2[i][1] = 0ull; }

#pragma unroll 4
    for (int hb = 0; hb < 16; hb++) {
        ulonglong2 xq[4];
#pragma unroll
        for (int i = 0; i < 4; i++)
            xq[i] = *(const ulonglong2*)(hid + (hb * 4 + i) * 128 + pg * 4);
#pragma unroll
        for (int om = 0; om < 18; om++) {
            float4 wv = *(const float4*)(wsp_s + (og * 18 + om) * 64 + hb * 4); // uniform bcast
            u64 w0 = pk(wv.x, wv.x), w1 = pk(wv.y, wv.y);
            u64 w2 = pk(wv.z, wv.z), w3 = pk(wv.w, wv.w);
            acc2[om][0] = ffma2(w0, xq[0].x, acc2[om][0]);
            acc2[om][1] = ffma2(w0, xq[0].y, acc2[om][1]);
            acc2[om][0] = ffma2(w1, xq[1].x, acc2[om][0]);
            acc2[om][1] = ffma2(w1, xq[1].y, acc2[om][1]);
            acc2[om][0] = ffma2(w2, xq[2].x, acc2[om][0]);
            acc2[om][1] = ffma2(w2, xq[2].y, acc2[om][1]);
            acc2[om][0] = ffma2(w3, xq[3].x, acc2[om][0]);
            acc2[om][1] = ffma2(w3, xq[3].y, acc2[om][1]);
        }
    }
#pragma unroll
    for (int om = 0; om < 18; om++) {
        int o = og * 18 + om;
        float bias = __ldg(bs + o);
        float4 r;
        r.x = lo32(acc2[om][0]) + bias;
        r.y = hi32(acc2[om][0]) + bias;
        r.z = lo32(acc2[om][1]) + bias;
        r.w = hi32(acc2[om][1]) + bias;
        *(float4*)(g_kmap + ((size_t)(b * GKK + o)) * HW + pt + pg * 4) = r;
    }
}

// ---------------------------------------------------------------------------
// Kernel 3: involution, full group (16 ch) per CTA, channel-pair interleaved.
// CTA = (strip of 8 rows, g, b). smem [8 chpair][10 rows][68 cols][2] = 43.5KB.
// 9 kmap LDG.128 hoisted to entry -> in flight across halo load + barrier.
// Halo stores are float2 (interleaved layout is only 8B-aligned there).
// ---------------------------------------------------------------------------
__global__ __launch_bounds__(256) void k_invol(const float* __restrict__ x,
                                               float* __restrict__ out) {
    __shared__ __align__(16) float sm[8 * 10 * 68 * 2];   // 43.5 KB
    const int tid   = threadIdx.x;
    const int strip = blockIdx.x;           // 0..7
    const int g = blockIdx.y;
    const int b = blockIdx.z;
    const int chbase = g * 16;

    const int cph = tid >> 7;          // 0..1
    const int rr  = (tid >> 4) & 7;    // output row within strip
    const int t4  = tid & 15;          // colgroup (4 cols)
    const int R0  = strip * 8 + rr;
    const int X0  = t4 * 4;

    // --- issue all 9 kmap loads immediately (hidden behind halo load) ---
    const float* kbase = g_kmap + ((size_t)(b * G + g)) * KK * HW + R0 * IMG_W + X0;
    float4 km[9];
#pragma unroll
    for (int k = 0; k < 9; k++)
        km[k] = *(const float4*)(kbase + (size_t)k * HW);

    // zero edge pair-columns (smem col 0 and 65) for all (cp, r)
    if (tid < 160) {
        int cp = tid / 20, rem = tid % 20;
        int r = rem >> 1, side = rem & 1;
        int col = side ? 65 : 0;
        *(u64*)&sm[((cp * 10 + r) * 68 + col) * 2] = 0ull;
    }

    // load 8 chpairs x 10 rows x 64 cols, interleaving channel pairs
#pragma unroll
    for (int it = 0; it < 5; it++) {
        int lin = tid + it * 256;          // 1280 items total
        int cp  = lin / 160;
        int rem = lin - cp * 160;
        int r = rem >> 4, c4 = rem & 15;
        int R = strip * 8 + r - 1;
        float4 a = make_float4(0.f, 0.f, 0.f, 0.f);
        float4 c = a;
        if ((unsigned)R < (unsigned)IMG_H) {
            const float* p0 = x + ((size_t)(b * C + chbase + cp * 2)) * HW + R * IMG_W + c4 * 4;
            a = *(const float4*)p0;
            c = *(const float4*)(p0 + HW);
        }
        float* d = &sm[((cp * 10 + r) * 68 + 1 + c4 * 4) * 2];  // 8B-aligned only
        ((float2*)d)[0] = make_float2(a.x, c.x);
        ((float2*)d)[1] = make_float2(a.y, c.y);
        ((float2*)d)[2] = make_float2(a.z, c.z);
        ((float2*)d)[3] = make_float2(a.w, c.w);
    }
    __syncthreads();

#pragma unroll
    for (int half = 0; half < 2; half++) {
        u64 acc[2][4];
#pragma unroll
        for (int cp = 0; cp < 2; cp++)
#pragma unroll
            for (int j = 0; j < 4; j++) acc[cp][j] = 0ull;

#pragma unroll
        for (int dy = 0; dy < 3; dy++) {
            u64 km2[3][4];
#pragma unroll
            for (int dx = 0; dx < 3; dx++) {
                float4 kmv = km[dy * 3 + dx];
                km2[dx][0] = pk(kmv.x, kmv.x);
                km2[dx][1] = pk(kmv.y, kmv.y);
                km2[dx][2] = pk(kmv.z, kmv.z);
                km2[dx][3] = pk(kmv.w, kmv.w);
            }
#pragma unroll
            for (int cp = 0; cp < 2; cp++) {
                const int cpi = cph * 4 + half * 2 + cp;
                const float* srow = &sm[((cpi * 10 + rr + dy) * 68 + t4 * 4) * 2];
                ulonglong2 q0 = *(const ulonglong2*)(srow);
                ulonglong2 q1 = *(const ulonglong2*)(srow + 4);
                ulonglong2 q2 = *(const ulonglong2*)(srow + 8);
                u64 p0 = q0.x, p1 = q0.y, p2 = q1.x, p3 = q1.y, p4 = q2.x, p5 = q2.y;
                acc[cp][0] = ffma2(p0, km2[0][0], acc[cp][0]);
                acc[cp][0] = ffma2(p1, km2[1][0], acc[cp][0]);
                acc[cp][0] = ffma2(p2, km2[2][0], acc[cp][0]);
                acc[cp][1] = ffma2(p1, km2[0][1], acc[cp][1]);
                acc[cp][1] = ffma2(p2, km2[1][1], acc[cp][1]);
                acc[cp][1] = ffma2(p3, km2[2][1], acc[cp][1]);
                acc[cp][2] = ffma2(p2, km2[0][2], acc[cp][2]);
                acc[cp][2] = ffma2(p3, km2[1][2], acc[cp][2]);
                acc[cp][2] = ffma2(p4, km2[2][2], acc[cp][2]);
                acc[cp][3] = ffma2(p3, km2[0][3], acc[cp][3]);
                acc[cp][3] = ffma2(p4, km2[1][3], acc[cp][3]);
                acc[cp][3] = ffma2(p5, km2[2][3], acc[cp][3]);
            }
        }

#pragma unroll
        for (int cp = 0; cp < 2; cp++) {
            const int ch = chbase + (cph * 4 + half * 2 + cp) * 2;
            float4 ev, od;
            ev.x = lo32(acc[cp][0]); od.x = hi32(acc[cp][0]);
            ev.y = lo32(acc[cp][1]); od.y = hi32(acc[cp][1]);
            ev.z = lo32(acc[cp][2]); od.z = hi32(acc[cp][2]);
            ev.w = lo32(acc[cp][3]); od.w = hi32(acc[cp][3]);
            float* obase = out + ((size_t)(b * C + ch)) * HW + R0 * IMG_W + X0;
            *(float4*)obase = ev;
            *(float4*)(obase + HW) = od;
        }
    }
}

// ---------------------------------------------------------------------------
extern "C" void kernel_launch(void* const* d_in, const int* in_sizes, int n_in,
                              void* d_out, int out_size) {
    const float* x   = (const float*)d_in[0];
    const float* wr  = (const float*)d_in[1];
    const float* br  = (const float*)d_in[2];
    const float* wsp = (const float*)d_in[3];
    const float* bs  = (const float*)d_in[4];
    float* out = (float*)d_out;

    static int smem_set = 0;
    if (!smem_set) {
        cudaFuncSetAttribute(k_fused, cudaFuncAttributeMaxDynamicSharedMemorySize, 86016);
        smem_set = 1;
    }

    k_fused<<<BB * (HW / 128), 256, 86016>>>(x, wr, br, wsp, bs);
    dim3 g3(8, G, BB);   // (strip, g, b)
    k_invol<<<g3, 256>>>(x, out);
}